// round 10
// baseline (speedup 1.0000x reference)
#include <cuda_runtime.h>
#include <cuda_bf16.h>
#include <cstdint>

// SkipGramMultiContext: B=16384, C_MAX=10, K_NEG=5, DIM=128, VOCAB=100000
// Output: float32[2] = {positive_loss, negative_loss}
//
// Half-warp-per-sample (lanes 0-15 = sample A, 16-31 = B) + PREDICATED
// gathers: only rows actually used by the loss are loaded.
//   context row r needed  iff r < len
//   negative rows needed  iff len > 0
// Mean rows/sample ~10.5 vs 16 -> ~34% less gather traffic.
// NOTE: __shfl_sync stays UNCONDITIONAL (all lanes execute); only the
// loads/dots are predicated. R8 crashed by putting the shfl in the branch.

#define B_SAMPLES 16384
#define C_MAX 10
#define K_NEG 5
#define DIM 128
#define NSCORE 15
#define WARPS_PER_BLOCK 8
#define THREADS (WARPS_PER_BLOCK * 32)
#define NWARPS (B_SAMPLES / 2)

__device__ __forceinline__ float neg_logsig(float x) {
    // -log(sigmoid(x)) = -min(x,0) + log(1 + exp(-|x|)); log arg in (1,2]
    return __logf(1.0f + __expf(-fabsf(x))) - fminf(x, 0.0f);
}

__device__ __forceinline__ float dot4(float4 a, float4 b) {
    return fmaf(a.x, b.x, fmaf(a.y, b.y, fmaf(a.z, b.z, a.w * b.w)));
}

__global__ void zero_out_kernel(float* out) {
    if (threadIdx.x < 2) out[threadIdx.x] = 0.0f;
}

__global__ __launch_bounds__(THREADS)
void skipgram_loss_kernel(const int* __restrict__ tw,
                          const int* __restrict__ cw,
                          const int* __restrict__ cl,
                          const int* __restrict__ nw,
                          const float* __restrict__ in_emb,
                          const float* __restrict__ out_emb,
                          float* __restrict__ out) {
    const int w     = (blockIdx.x * THREADS + threadIdx.x) >> 5;
    const int lane  = threadIdx.x & 31;
    const int h     = lane >> 4;       // 0 = sample A, 1 = sample B
    const int hlane = lane & 15;
    const int wib   = threadIdx.x >> 5;

    __shared__ float s_pos[WARPS_PER_BLOCK];
    __shared__ float s_neg[WARPS_PER_BLOCK];

    const int b = 2 * w + h;           // this half-warp's sample

    // per-half indices: hlane 0..9 ctx, 10..14 neg
    int idx = 0;
    if (hlane < C_MAX)       idx = __ldg(&cw[b * C_MAX + hlane]);
    else if (hlane < NSCORE) idx = __ldg(&nw[b * K_NEG + (hlane - C_MAX)]);
    const int len = __ldg(&cl[b]);
    const bool has_ctx = (len > 0);

    // target row slices (predicated: only needed when len > 0; address always valid)
    const int trow = __ldg(&tw[b]);
    const float4* trow4 = reinterpret_cast<const float4*>(in_emb + (size_t)trow * DIM);
    float4 t0 = make_float4(0.f, 0.f, 0.f, 0.f);
    float4 t1 = t0;
    if (has_ctx) {
        t0 = trow4[hlane];
        t1 = trow4[16 + hlane];
    }

    // predicated row gathers; shfl ALWAYS executed by all lanes
    float v[16];
    #pragma unroll
    for (int r = 0; r < NSCORE; r++) {
        const int row = __shfl_sync(0xffffffffu, idx, (h << 4) + r);  // convergent
        const bool need = (r < C_MAX) ? (r < len) : has_ctx;
        float d = 0.0f;
        if (need) {
            const float4* c4 = reinterpret_cast<const float4*>(out_emb + (size_t)row * DIM);
            d = dot4(t0, c4[hlane]) + dot4(t1, c4[16 + hlane]);
        }
        v[r] = d;
    }
    v[15] = 0.0f;

    // Width-16 multi-value tree (offsets 8,4,2,1): XOR partners stay within
    // each half. After it, lane (h*16 + r) holds the full 16-lane sum of v[r].
    #pragma unroll
    for (int o = 8, nn = 8; o > 0; o >>= 1, nn >>= 1) {
        const bool up = (lane & o) != 0;
        #pragma unroll
        for (int i = 0; i < 8; i++) {
            if (i < nn) {
                const float send = up ? v[i] : v[i + nn];
                const float keep = up ? v[i + nn] : v[i];
                v[i] = keep + __shfl_xor_sync(0xffffffffu, send, o);
            }
        }
    }
    const float score = v[0];          // score index r = hlane

    // per-lane contribution, pre-normalized per sample
    float pv = 0.0f, nv = 0.0f;
    if (hlane < C_MAX) {
        if (hlane < len) pv = neg_logsig(score) / (float)len;     // len >= 1 here
    } else if (hlane < NSCORE) {
        if (has_ctx) nv = neg_logsig(-score) * (1.0f / (float)K_NEG);
    }

    // butterfly within half (8,4,2,1) then merge halves (16)
    #pragma unroll
    for (int o = 8; o > 0; o >>= 1) {
        pv += __shfl_xor_sync(0xffffffffu, pv, o);
        nv += __shfl_xor_sync(0xffffffffu, nv, o);
    }
    pv += __shfl_xor_sync(0xffffffffu, pv, 16);
    nv += __shfl_xor_sync(0xffffffffu, nv, 16);

    if (lane == 0) {
        s_pos[wib] = pv;
        s_neg[wib] = nv;
    }
    __syncthreads();

    if (threadIdx.x == 0) {
        float ps = 0.0f, ns = 0.0f;
        #pragma unroll
        for (int ww = 0; ww < WARPS_PER_BLOCK; ww++) { ps += s_pos[ww]; ns += s_neg[ww]; }
        const float invB = 1.0f / (float)B_SAMPLES;
        atomicAdd(&out[0], ps * invB);
        atomicAdd(&out[1], ns * invB);
    }
}

extern "C" void kernel_launch(void* const* d_in, const int* in_sizes, int n_in,
                              void* d_out, int out_size) {
    const int*   tw      = (const int*)d_in[0];
    const int*   cw      = (const int*)d_in[1];
    const int*   cl      = (const int*)d_in[2];
    const int*   nw      = (const int*)d_in[3];
    const float* in_emb  = (const float*)d_in[4];
    const float* out_emb = (const float*)d_in[5];
    float* out = (float*)d_out;

    zero_out_kernel<<<1, 32>>>(out);

    const int num_blocks = NWARPS / WARPS_PER_BLOCK;   // 1024
    skipgram_loss_kernel<<<num_blocks, THREADS>>>(tw, cw, cl, nw, in_emb, out_emb, out);
}

// round 11
// speedup vs baseline: 1.4190x; 1.4190x over previous
#include <cuda_runtime.h>
#include <cuda_bf16.h>
#include <cstdint>

// SkipGramMultiContext: B=16384, C_MAX=10, K_NEG=5, DIM=128, VOCAB=100000
// Output: float32[2] = {positive_loss, negative_loss}
//
// R6 half-warp-per-sample structure (lanes 0-15 = sample A, 16-31 = B;
// one width-16 tree reduction serves both samples) + BRANCH-FREE gather
// thinning: rows not needed by the loss are redirected to vocab row 0
// (L1-resident broadcast) via a single SEL, preserving the fully batched
// unconditional load schedule that R9's branchy predication destroyed.

#define B_SAMPLES 16384
#define C_MAX 10
#define K_NEG 5
#define DIM 128
#define NSCORE 15
#define WARPS_PER_BLOCK 8
#define THREADS (WARPS_PER_BLOCK * 32)
#define NWARPS (B_SAMPLES / 2)

__device__ __forceinline__ float neg_logsig(float x) {
    // -log(sigmoid(x)) = -min(x,0) + log(1 + exp(-|x|)); log arg in (1,2]
    return __logf(1.0f + __expf(-fabsf(x))) - fminf(x, 0.0f);
}

__device__ __forceinline__ float dot4(float4 a, float4 b) {
    return fmaf(a.x, b.x, fmaf(a.y, b.y, fmaf(a.z, b.z, a.w * b.w)));
}

__global__ void zero_out_kernel(float* out) {
    if (threadIdx.x < 2) out[threadIdx.x] = 0.0f;
}

__global__ __launch_bounds__(THREADS)
void skipgram_loss_kernel(const int* __restrict__ tw,
                          const int* __restrict__ cw,
                          const int* __restrict__ cl,
                          const int* __restrict__ nw,
                          const float* __restrict__ in_emb,
                          const float* __restrict__ out_emb,
                          float* __restrict__ out) {
    const int w     = (blockIdx.x * THREADS + threadIdx.x) >> 5;
    const int lane  = threadIdx.x & 31;
    const int h     = lane >> 4;       // 0 = sample A, 1 = sample B
    const int hlane = lane & 15;
    const int wib   = threadIdx.x >> 5;

    __shared__ float s_pos[WARPS_PER_BLOCK];
    __shared__ float s_neg[WARPS_PER_BLOCK];

    const int b = 2 * w + h;           // this half-warp's sample

    // per-half indices: hlane 0..9 ctx, 10..14 neg
    int idx = 0;
    if (hlane < C_MAX)       idx = __ldg(&cw[b * C_MAX + hlane]);
    else if (hlane < NSCORE) idx = __ldg(&nw[b * K_NEG + (hlane - C_MAX)]);
    const int len = __ldg(&cl[b]);
    const bool has_ctx = (len > 0);

    // target row: redirected to row 0 when unused (branch-free)
    const int trow = has_ctx ? __ldg(&tw[b]) : 0;
    const float4* trow4 = reinterpret_cast<const float4*>(in_emb + (size_t)trow * DIM);
    const float4 t0 = trow4[hlane];
    const float4 t1 = trow4[16 + hlane];

    // 15 unconditional, fully batched row gathers; dead rows -> row 0 (L1 hit)
    float v[16];
    #pragma unroll
    for (int r = 0; r < NSCORE; r++) {
        const int row_raw = __shfl_sync(0xffffffffu, idx, (h << 4) + r);  // convergent
        const bool need = (r < C_MAX) ? (r < len) : has_ctx;
        const int row = need ? row_raw : 0;                                // 1 SEL
        const float4* c4 = reinterpret_cast<const float4*>(out_emb + (size_t)row * DIM);
        v[r] = dot4(t0, c4[hlane]) + dot4(t1, c4[16 + hlane]);
        // garbage when !need; masked in the epilogue exactly as in R6
    }
    v[15] = 0.0f;

    // Width-16 multi-value tree (offsets 8,4,2,1): XOR partners stay within
    // each half. After it, lane (h*16 + r) holds the full 16-lane sum of v[r].
    #pragma unroll
    for (int o = 8, nn = 8; o > 0; o >>= 1, nn >>= 1) {
        const bool up = (lane & o) != 0;
        #pragma unroll
        for (int i = 0; i < 8; i++) {
            if (i < nn) {
                const float send = up ? v[i] : v[i + nn];
                const float keep = up ? v[i + nn] : v[i];
                v[i] = keep + __shfl_xor_sync(0xffffffffu, send, o);
            }
        }
    }
    const float score = v[0];          // score index r = hlane

    // per-lane contribution, pre-normalized per sample (masks dead scores)
    float pv = 0.0f, nv = 0.0f;
    if (hlane < C_MAX) {
        if (hlane < len) pv = neg_logsig(score) / (float)len;     // len >= 1 here
    } else if (hlane < NSCORE) {
        if (has_ctx) nv = neg_logsig(-score) * (1.0f / (float)K_NEG);
    }

    // butterfly within half (8,4,2,1) then merge halves (16)
    #pragma unroll
    for (int o = 8; o > 0; o >>= 1) {
        pv += __shfl_xor_sync(0xffffffffu, pv, o);
        nv += __shfl_xor_sync(0xffffffffu, nv, o);
    }
    pv += __shfl_xor_sync(0xffffffffu, pv, 16);
    nv += __shfl_xor_sync(0xffffffffu, nv, 16);

    if (lane == 0) {
        s_pos[wib] = pv;
        s_neg[wib] = nv;
    }
    __syncthreads();

    if (threadIdx.x == 0) {
        float ps = 0.0f, ns = 0.0f;
        #pragma unroll
        for (int ww = 0; ww < WARPS_PER_BLOCK; ww++) { ps += s_pos[ww]; ns += s_neg[ww]; }
        const float invB = 1.0f / (float)B_SAMPLES;
        atomicAdd(&out[0], ps * invB);
        atomicAdd(&out[1], ns * invB);
    }
}

extern "C" void kernel_launch(void* const* d_in, const int* in_sizes, int n_in,
                              void* d_out, int out_size) {
    const int*   tw      = (const int*)d_in[0];
    const int*   cw      = (const int*)d_in[1];
    const int*   cl      = (const int*)d_in[2];
    const int*   nw      = (const int*)d_in[3];
    const float* in_emb  = (const float*)d_in[4];
    const float* out_emb = (const float*)d_in[5];
    float* out = (float*)d_out;

    zero_out_kernel<<<1, 32>>>(out);

    const int num_blocks = NWARPS / WARPS_PER_BLOCK;   // 1024
    skipgram_loss_kernel<<<num_blocks, THREADS>>>(tw, cw, cl, nw, in_emb, out_emb, out);
}